// round 1
// baseline (speedup 1.0000x reference)
#include <cuda_runtime.h>
#include <math.h>

// Problem constants
#define D_MODEL 1024
#define NUM_HEADS 16
#define DK 64
#define BATCH 4
#define SEQ 2048
#define MTOT (BATCH * SEQ)   // 8192

// Scratch: intermediates live in __device__ globals (no allocation allowed).
__device__ float g_Q[MTOT * D_MODEL];
__device__ float g_K[MTOT * D_MODEL];
__device__ float g_V[MTOT * D_MODEL];
__device__ float g_O[MTOT * D_MODEL];

// ---------------------------------------------------------------------------
// GEMM: C[M,N] = A[M,K] @ W[N,K]^T + bias[N]
// 128x128 tile, BK=8, 256 threads, 8x8 register tile/thread.
// ---------------------------------------------------------------------------
#define BM 128
#define BN 128
#define BKC 8

__global__ __launch_bounds__(256) void gemm_xwT_bias(
    const float* __restrict__ A, const float* __restrict__ W,
    const float* __restrict__ bias, float* __restrict__ C,
    int M, int N, int K)
{
    __shared__ float As[BKC][BM + 4];
    __shared__ float Bs[BKC][BN + 4];

    const int tid = threadIdx.x;
    const int tx = tid & 15;        // 0..15
    const int ty = tid >> 4;        // 0..15
    const int row0 = blockIdx.y * BM;
    const int col0 = blockIdx.x * BN;

    const int lr = tid >> 1;        // 0..127 : row within tile to load
    const int lk = (tid & 1) * 4;   // 0 or 4 : k-offset to load

    const float* Ag = A + (size_t)(row0 + lr) * K + lk;
    const float* Wg = W + (size_t)(col0 + lr) * K + lk;

    float acc[8][8];
#pragma unroll
    for (int i = 0; i < 8; i++)
#pragma unroll
        for (int j = 0; j < 8; j++) acc[i][j] = 0.0f;

    for (int k0 = 0; k0 < K; k0 += BKC) {
        float4 a = *(const float4*)(Ag + k0);
        float4 b = *(const float4*)(Wg + k0);
        As[lk + 0][lr] = a.x; As[lk + 1][lr] = a.y;
        As[lk + 2][lr] = a.z; As[lk + 3][lr] = a.w;
        Bs[lk + 0][lr] = b.x; Bs[lk + 1][lr] = b.y;
        Bs[lk + 2][lr] = b.z; Bs[lk + 3][lr] = b.w;
        __syncthreads();

#pragma unroll
        for (int k = 0; k < BKC; k++) {
            float4 a0 = *(const float4*)&As[k][ty * 8 + 0];
            float4 a1 = *(const float4*)&As[k][ty * 8 + 4];
            float4 b0 = *(const float4*)&Bs[k][tx * 8 + 0];
            float4 b1 = *(const float4*)&Bs[k][tx * 8 + 4];
            float ra[8] = {a0.x, a0.y, a0.z, a0.w, a1.x, a1.y, a1.z, a1.w};
            float rb[8] = {b0.x, b0.y, b0.z, b0.w, b1.x, b1.y, b1.z, b1.w};
#pragma unroll
            for (int i = 0; i < 8; i++)
#pragma unroll
                for (int j = 0; j < 8; j++)
                    acc[i][j] = fmaf(ra[i], rb[j], acc[i][j]);
        }
        __syncthreads();
    }

    // Epilogue: add bias, store
    float4 bv0 = *(const float4*)&bias[col0 + tx * 8 + 0];
    float4 bv1 = *(const float4*)&bias[col0 + tx * 8 + 4];
#pragma unroll
    for (int i = 0; i < 8; i++) {
        int r = row0 + ty * 8 + i;
        float* Cr = C + (size_t)r * N + col0 + tx * 8;
        float4 o0 = make_float4(acc[i][0] + bv0.x, acc[i][1] + bv0.y,
                                acc[i][2] + bv0.z, acc[i][3] + bv0.w);
        float4 o1 = make_float4(acc[i][4] + bv1.x, acc[i][5] + bv1.y,
                                acc[i][6] + bv1.z, acc[i][7] + bv1.w);
        *(float4*)(Cr + 0) = o0;
        *(float4*)(Cr + 4) = o1;
    }
}

// ---------------------------------------------------------------------------
// Flash attention: one CTA per (b, h, 64-query tile). Br=Bc=64, d=64.
// Q/K/V read directly from merged [B*S, 1024] layout with column offset h*64.
// O written directly merged -> no transpose kernels needed.
// ---------------------------------------------------------------------------
#define APITCH 68   // smem row pitch (floats): multiple of 4, bank-skewed

__global__ __launch_bounds__(256) void flash_attn(
    const float* __restrict__ Q, const float* __restrict__ K,
    const float* __restrict__ V, float* __restrict__ O)
{
    extern __shared__ float sm[];
    float* Qs = sm;                 // 64 * APITCH
    float* Ks = Qs + 64 * APITCH;
    float* Vs = Ks + 64 * APITCH;
    float* Ps = Vs + 64 * APITCH;

    const int tid = threadIdx.x;
    const int tx = tid & 15;   // 0..15 -> 4 cols each
    const int ty = tid >> 4;   // 0..15 -> 4 rows each
    const int bh = blockIdx.y;
    const int b = bh >> 4;
    const int h = bh & 15;
    const int q0 = blockIdx.x * 64;

    const float scale = 0.125f;  // 1/sqrt(64)
    const size_t base = (size_t)b * SEQ * D_MODEL + (size_t)h * DK;

    // Load Q tile (scaled). 64 rows x 16 float4s.
    for (int i = tid; i < 64 * 16; i += 256) {
        int r = i >> 4, c4 = (i & 15) * 4;
        float4 qv = *(const float4*)(Q + base + (size_t)(q0 + r) * D_MODEL + c4);
        qv.x *= scale; qv.y *= scale; qv.z *= scale; qv.w *= scale;
        *(float4*)&Qs[r * APITCH + c4] = qv;
    }

    float m[4], l[4], acc[4][4];
#pragma unroll
    for (int i = 0; i < 4; i++) {
        m[i] = -INFINITY; l[i] = 0.0f;
#pragma unroll
        for (int j = 0; j < 4; j++) acc[i][j] = 0.0f;
    }

    for (int kb = 0; kb < SEQ / 64; kb++) {
        __syncthreads();  // previous PV done (also covers Qs on first iter)
        // Load K, V tiles
        for (int i = tid; i < 64 * 16; i += 256) {
            int r = i >> 4, c4 = (i & 15) * 4;
            size_t g = base + (size_t)(kb * 64 + r) * D_MODEL + c4;
            *(float4*)&Ks[r * APITCH + c4] = *(const float4*)(K + g);
            *(float4*)&Vs[r * APITCH + c4] = *(const float4*)(V + g);
        }
        __syncthreads();

        // S = Qs @ Ks^T  (4x4 per thread over d=64)
        float s[4][4];
#pragma unroll
        for (int i = 0; i < 4; i++)
#pragma unroll
            for (int j = 0; j < 4; j++) s[i][j] = 0.0f;

#pragma unroll
        for (int d4 = 0; d4 < 16; d4++) {
            float4 qa[4], ka[4];
#pragma unroll
            for (int ii = 0; ii < 4; ii++)
                qa[ii] = *(const float4*)&Qs[(4 * ty + ii) * APITCH + d4 * 4];
#pragma unroll
            for (int jj = 0; jj < 4; jj++)
                ka[jj] = *(const float4*)&Ks[(4 * tx + jj) * APITCH + d4 * 4];
#pragma unroll
            for (int ii = 0; ii < 4; ii++)
#pragma unroll
                for (int jj = 0; jj < 4; jj++) {
                    s[ii][jj] = fmaf(qa[ii].x, ka[jj].x, s[ii][jj]);
                    s[ii][jj] = fmaf(qa[ii].y, ka[jj].y, s[ii][jj]);
                    s[ii][jj] = fmaf(qa[ii].z, ka[jj].z, s[ii][jj]);
                    s[ii][jj] = fmaf(qa[ii].w, ka[jj].w, s[ii][jj]);
                }
        }

        // Online softmax per row (rows owned by same (ty): reduce across tx)
#pragma unroll
        for (int ii = 0; ii < 4; ii++) {
            float rmax = fmaxf(fmaxf(s[ii][0], s[ii][1]), fmaxf(s[ii][2], s[ii][3]));
#pragma unroll
            for (int off = 8; off > 0; off >>= 1)
                rmax = fmaxf(rmax, __shfl_xor_sync(0xffffffffu, rmax, off, 16));
            float mnew = fmaxf(m[ii], rmax);
            float p0 = __expf(s[ii][0] - mnew);
            float p1 = __expf(s[ii][1] - mnew);
            float p2 = __expf(s[ii][2] - mnew);
            float p3 = __expf(s[ii][3] - mnew);
            float rsum = p0 + p1 + p2 + p3;
#pragma unroll
            for (int off = 8; off > 0; off >>= 1)
                rsum += __shfl_xor_sync(0xffffffffu, rsum, off, 16);
            float alpha = __expf(m[ii] - mnew);
            l[ii] = l[ii] * alpha + rsum;
            m[ii] = mnew;
#pragma unroll
            for (int jj = 0; jj < 4; jj++) acc[ii][jj] *= alpha;
            *(float4*)&Ps[(4 * ty + ii) * APITCH + 4 * tx] =
                make_float4(p0, p1, p2, p3);
        }
        __syncthreads();

        // acc += Ps @ Vs   (inner over j=64)
#pragma unroll
        for (int j4 = 0; j4 < 16; j4++) {
            float4 pr[4], vr[4];
#pragma unroll
            for (int ii = 0; ii < 4; ii++)
                pr[ii] = *(const float4*)&Ps[(4 * ty + ii) * APITCH + j4 * 4];
#pragma unroll
            for (int t = 0; t < 4; t++)
                vr[t] = *(const float4*)&Vs[(j4 * 4 + t) * APITCH + 4 * tx];
#pragma unroll
            for (int ii = 0; ii < 4; ii++) {
                acc[ii][0] = fmaf(pr[ii].x, vr[0].x, acc[ii][0]);
                acc[ii][1] = fmaf(pr[ii].x, vr[0].y, acc[ii][1]);
                acc[ii][2] = fmaf(pr[ii].x, vr[0].z, acc[ii][2]);
                acc[ii][3] = fmaf(pr[ii].x, vr[0].w, acc[ii][3]);
                acc[ii][0] = fmaf(pr[ii].y, vr[1].x, acc[ii][0]);
                acc[ii][1] = fmaf(pr[ii].y, vr[1].y, acc[ii][1]);
                acc[ii][2] = fmaf(pr[ii].y, vr[1].z, acc[ii][2]);
                acc[ii][3] = fmaf(pr[ii].y, vr[1].w, acc[ii][3]);
                acc[ii][0] = fmaf(pr[ii].z, vr[2].x, acc[ii][0]);
                acc[ii][1] = fmaf(pr[ii].z, vr[2].y, acc[ii][1]);
                acc[ii][2] = fmaf(pr[ii].z, vr[2].z, acc[ii][2]);
                acc[ii][3] = fmaf(pr[ii].z, vr[2].w, acc[ii][3]);
                acc[ii][0] = fmaf(pr[ii].w, vr[3].x, acc[ii][0]);
                acc[ii][1] = fmaf(pr[ii].w, vr[3].y, acc[ii][1]);
                acc[ii][2] = fmaf(pr[ii].w, vr[3].z, acc[ii][2]);
                acc[ii][3] = fmaf(pr[ii].w, vr[3].w, acc[ii][3]);
            }
        }
    }

    // Write O (merged layout)
#pragma unroll
    for (int ii = 0; ii < 4; ii++) {
        float inv = 1.0f / l[ii];
        float4 o = make_float4(acc[ii][0] * inv, acc[ii][1] * inv,
                               acc[ii][2] * inv, acc[ii][3] * inv);
        *(float4*)(O + base + (size_t)(q0 + 4 * ty + ii) * D_MODEL + 4 * tx) = o;
    }
}

// ---------------------------------------------------------------------------
// Launch
// ---------------------------------------------------------------------------
extern "C" void kernel_launch(void* const* d_in, const int* in_sizes, int n_in,
                              void* d_out, int out_size)
{
    const float* q  = (const float*)d_in[0];
    const float* k  = (const float*)d_in[1];
    const float* v  = (const float*)d_in[2];
    const float* Wq = (const float*)d_in[3];
    const float* bq = (const float*)d_in[4];
    const float* Wk = (const float*)d_in[5];
    const float* bk = (const float*)d_in[6];
    const float* Wv = (const float*)d_in[7];
    const float* bv = (const float*)d_in[8];
    const float* Wo = (const float*)d_in[9];
    const float* bo = (const float*)d_in[10];
    float* out = (float*)d_out;

    float *pQ, *pK, *pV, *pO;
    cudaGetSymbolAddress((void**)&pQ, g_Q);
    cudaGetSymbolAddress((void**)&pK, g_K);
    cudaGetSymbolAddress((void**)&pV, g_V);
    cudaGetSymbolAddress((void**)&pO, g_O);

    const int smem_attn = 4 * 64 * APITCH * sizeof(float);  // 69632 B
    cudaFuncSetAttribute(flash_attn, cudaFuncAttributeMaxDynamicSharedMemorySize,
                         smem_attn);

    dim3 gGemm(D_MODEL / BN, MTOT / BM);  // (8, 64)
    gemm_xwT_bias<<<gGemm, 256>>>(q, Wq, bq, pQ, MTOT, D_MODEL, D_MODEL);
    gemm_xwT_bias<<<gGemm, 256>>>(k, Wk, bk, pK, MTOT, D_MODEL, D_MODEL);
    gemm_xwT_bias<<<gGemm, 256>>>(v, Wv, bv, pV, MTOT, D_MODEL, D_MODEL);

    dim3 gAttn(SEQ / 64, BATCH * NUM_HEADS);  // (32, 64)
    flash_attn<<<gAttn, 256, smem_attn>>>(pQ, pK, pV, pO);

    gemm_xwT_bias<<<gGemm, 256>>>(pO, Wo, bo, out, MTOT, D_MODEL, D_MODEL);
}

// round 3
// speedup vs baseline: 4.2707x; 4.2707x over previous
#include <cuda_runtime.h>
#include <math.h>
#include <stdint.h>

#define D_MODEL 1024
#define NUM_HEADS 16
#define DK 64
#define BATCH 4
#define SEQ 2048
#define MTOT (BATCH * SEQ)   // 8192

// Scratch (no allocation allowed)
__device__ float g_Q[MTOT * D_MODEL];
__device__ float g_K[MTOT * D_MODEL];
__device__ float g_V[MTOT * D_MODEL];
__device__ float g_O[MTOT * D_MODEL];

// ---------------------------------------------------------------------------
// Helpers: tf32 round-to-nearest, legacy mma.sync (NOT 'a'-gated), cp.async
// ---------------------------------------------------------------------------
__device__ __forceinline__ uint32_t f2tf32(float x) {
    uint32_t r;
    asm("cvt.rn.tf32.f32 %0, %1;" : "=r"(r) : "f"(x));
    return r;
}
__device__ __forceinline__ float f2tf32f(float x) {
    return __uint_as_float(f2tf32(x));
}

// D += A*B : m16n8k8 tf32. a regs: (g,tig),(g+8,tig),(g,tig+4),(g+8,tig+4)
// b regs: (tig,g),(tig+4,g). c regs: (g,2tig),(g,2tig+1),(g+8,2tig),(g+8,2tig+1)
__device__ __forceinline__ void mma8(float c[4], uint32_t a0, uint32_t a1,
                                     uint32_t a2, uint32_t a3,
                                     uint32_t b0, uint32_t b1) {
    asm volatile(
        "mma.sync.aligned.m16n8k8.row.col.f32.tf32.tf32.f32 "
        "{%0,%1,%2,%3}, {%4,%5,%6,%7}, {%8,%9}, {%0,%1,%2,%3};"
        : "+f"(c[0]), "+f"(c[1]), "+f"(c[2]), "+f"(c[3])
        : "r"(a0), "r"(a1), "r"(a2), "r"(a3), "r"(b0), "r"(b1));
}

__device__ __forceinline__ void cp_async16(void* smem, const void* gmem) {
    uint32_t s = (uint32_t)__cvta_generic_to_shared(smem);
    asm volatile("cp.async.cg.shared.global [%0], [%1], 16;" :: "r"(s), "l"(gmem));
}
__device__ __forceinline__ void cp_commit() {
    asm volatile("cp.async.commit_group;");
}
template <int N>
__device__ __forceinline__ void cp_wait() {
    asm volatile("cp.async.wait_group %0;" :: "n"(N));
}

__device__ __forceinline__ uint32_t fbits(float x) { return __float_as_uint(x); }

// ---------------------------------------------------------------------------
// GEMM: C[8192,1024] = A[8192,1024] @ W[1024,1024]^T + bias, tf32 mma.
// CTA 128x128, 8 warps (4x2), warp tile 32x64, BK=16, reg-staged double buffer.
// round_out=1 -> outputs rounded to tf32 RN (feeds attention's raw-bit path).
// ---------------------------------------------------------------------------
#define GP 20   // smem pitch (floats): conflict-free for frag reads

__global__ __launch_bounds__(256, 2) void gemm_mma(
    const float* __restrict__ A, const float* __restrict__ W,
    const float* __restrict__ bias, float* __restrict__ C, int round_out)
{
    __shared__ float As[2][128 * GP];
    __shared__ float Ws[2][128 * GP];

    const int KD = D_MODEL, ND = D_MODEL;
    const int tid = threadIdx.x;
    const int lane = tid & 31;
    const int g = lane >> 2, tig = lane & 3;
    const int wid = tid >> 5;
    const int wm = wid & 3;      // 0..3 -> 32-row block
    const int wn = wid >> 2;     // 0..1 -> 64-col block
    const int row0 = blockIdx.y * 128;
    const int col0 = blockIdx.x * 128;

    // load slots: 512 float4 per matrix per chunk; 2 per thread
    const int r0 = tid >> 2,          c0 = (tid & 3) * 4;
    const int r1 = (tid + 256) >> 2,  c1 = (tid & 3) * 4;  // rows 64..127

    const float* Ag = A + (size_t)row0 * KD;
    const float* Wg = W + (size_t)col0 * KD;

    float4 av0, av1, wv0, wv1;
    av0 = *(const float4*)(Ag + (size_t)r0 * KD + c0);
    av1 = *(const float4*)(Ag + (size_t)r1 * KD + c1);
    wv0 = *(const float4*)(Wg + (size_t)r0 * KD + c0);
    wv1 = *(const float4*)(Wg + (size_t)r1 * KD + c1);

    float acc[2][8][4];
#pragma unroll
    for (int mt = 0; mt < 2; mt++)
#pragma unroll
        for (int nt = 0; nt < 8; nt++)
#pragma unroll
            for (int i = 0; i < 4; i++) acc[mt][nt][i] = 0.0f;

    for (int ch = 0; ch < 64; ch++) {
        const int p = ch & 1;
        // store staged chunk (tf32 RN)
        {
            float4 t;
            t = av0;
            *(float4*)&As[p][r0 * GP + c0] = make_float4(
                f2tf32f(t.x), f2tf32f(t.y), f2tf32f(t.z), f2tf32f(t.w));
            t = av1;
            *(float4*)&As[p][r1 * GP + c1] = make_float4(
                f2tf32f(t.x), f2tf32f(t.y), f2tf32f(t.z), f2tf32f(t.w));
            t = wv0;
            *(float4*)&Ws[p][r0 * GP + c0] = make_float4(
                f2tf32f(t.x), f2tf32f(t.y), f2tf32f(t.z), f2tf32f(t.w));
            t = wv1;
            *(float4*)&Ws[p][r1 * GP + c1] = make_float4(
                f2tf32f(t.x), f2tf32f(t.y), f2tf32f(t.z), f2tf32f(t.w));
        }
        __syncthreads();

        if (ch < 63) {  // stage next chunk (overlaps with compute)
            const int ko = (ch + 1) * 16;
            av0 = *(const float4*)(Ag + (size_t)r0 * KD + ko + c0);
            av1 = *(const float4*)(Ag + (size_t)r1 * KD + ko + c1);
            wv0 = *(const float4*)(Wg + (size_t)r0 * KD + ko + c0);
            wv1 = *(const float4*)(Wg + (size_t)r1 * KD + ko + c1);
        }

#pragma unroll
        for (int kk = 0; kk < 2; kk++) {
            uint32_t ua[2][4];
#pragma unroll
            for (int mt = 0; mt < 2; mt++) {
                const int rb = wm * 32 + mt * 16;
                ua[mt][0] = fbits(As[p][(rb + g) * GP + kk * 8 + tig]);
                ua[mt][1] = fbits(As[p][(rb + g + 8) * GP + kk * 8 + tig]);
                ua[mt][2] = fbits(As[p][(rb + g) * GP + kk * 8 + tig + 4]);
                ua[mt][3] = fbits(As[p][(rb + g + 8) * GP + kk * 8 + tig + 4]);
            }
#pragma unroll
            for (int nt = 0; nt < 8; nt++) {
                const int nb = wn * 64 + nt * 8;
                uint32_t b0 = fbits(Ws[p][(nb + g) * GP + kk * 8 + tig]);
                uint32_t b1 = fbits(Ws[p][(nb + g) * GP + kk * 8 + tig + 4]);
                mma8(acc[0][nt], ua[0][0], ua[0][1], ua[0][2], ua[0][3], b0, b1);
                mma8(acc[1][nt], ua[1][0], ua[1][1], ua[1][2], ua[1][3], b0, b1);
            }
        }
        __syncthreads();
    }

    // Epilogue
#pragma unroll
    for (int mt = 0; mt < 2; mt++) {
        const int ra = row0 + wm * 32 + mt * 16 + g;
#pragma unroll
        for (int nt = 0; nt < 8; nt++) {
            const int col = col0 + wn * 64 + nt * 8 + 2 * tig;
            const float bz0 = bias[col], bz1 = bias[col + 1];
            float v0 = acc[mt][nt][0] + bz0, v1 = acc[mt][nt][1] + bz1;
            float v2 = acc[mt][nt][2] + bz0, v3 = acc[mt][nt][3] + bz1;
            if (round_out) {
                v0 = f2tf32f(v0); v1 = f2tf32f(v1);
                v2 = f2tf32f(v2); v3 = f2tf32f(v3);
            }
            *(float2*)(C + (size_t)ra * ND + col) = make_float2(v0, v1);
            *(float2*)(C + (size_t)(ra + 8) * ND + col) = make_float2(v2, v3);
        }
    }
}

// ---------------------------------------------------------------------------
// Flash attention with tf32 mma: CTA per (b, h, 128 q-rows). Bc=64.
// Inputs pre-rounded to tf32 (projection epilogues), so cp.async raw bits ok.
// smem: P[128x68] (also Q staging) | K[2][64x68] | V[2][64x72]
// ---------------------------------------------------------------------------
#define KP 68
#define VP 72
#define PP 68
#define ATTN_SMEM ((128 * PP + 2 * 64 * KP + 2 * 64 * VP) * 4)  // 106496 B

__global__ __launch_bounds__(256, 1) void attn_mma(
    const float* __restrict__ Q, const float* __restrict__ K,
    const float* __restrict__ V, float* __restrict__ O)
{
    extern __shared__ float smf[];
    float* Ps = smf;                    // 128*PP
    float* Ks = Ps + 128 * PP;          // 2 * 64*KP
    float* Vs = Ks + 2 * 64 * KP;       // 2 * 64*VP

    const int tid = threadIdx.x;
    const int lane = tid & 31;
    const int g = lane >> 2, tig = lane & 3;
    const int wid = tid >> 5;
    const int qb = wid * 16;            // warp's q-row base within tile

    const int b = blockIdx.y >> 4;
    const int h = blockIdx.y & 15;
    const int q0 = blockIdx.x * 128;
    const size_t base = (size_t)b * SEQ * D_MODEL + (size_t)h * DK;

    // Stage Q (scaled) into Ps, then lift fragments to registers.
    for (int i = tid; i < 128 * 16; i += 256) {
        int r = i >> 4, c4 = (i & 15) * 4;
        float4 qv = *(const float4*)(Q + base + (size_t)(q0 + r) * D_MODEL + c4);
        qv.x *= 0.125f; qv.y *= 0.125f; qv.z *= 0.125f; qv.w *= 0.125f;
        *(float4*)&Ps[r * PP + c4] = qv;
    }
    __syncthreads();
    uint32_t qa[8][4];
#pragma unroll
    for (int kk = 0; kk < 8; kk++) {
        qa[kk][0] = fbits(Ps[(qb + g) * PP + kk * 8 + tig]);
        qa[kk][1] = fbits(Ps[(qb + g + 8) * PP + kk * 8 + tig]);
        qa[kk][2] = fbits(Ps[(qb + g) * PP + kk * 8 + tig + 4]);
        qa[kk][3] = fbits(Ps[(qb + g + 8) * PP + kk * 8 + tig + 4]);
    }
    __syncthreads();

    // cp.async K/V block loader: 64 rows x 16 float4 each
    auto load_blk = [&](int kb, int p) {
#pragma unroll
        for (int j = 0; j < 4; j++) {
            int slot = tid + j * 256;
            int r = slot >> 4, c4 = (slot & 15) * 4;
            const float* kg = K + base + (size_t)(kb * 64 + r) * D_MODEL + c4;
            const float* vg = V + base + (size_t)(kb * 64 + r) * D_MODEL + c4;
            cp_async16(&Ks[p * 64 * KP + r * KP + c4], kg);
            cp_async16(&Vs[p * 64 * VP + r * VP + c4], vg);
        }
        cp_commit();
    };
    load_blk(0, 0);
    load_blk(1, 1);

    float m0 = -INFINITY, m1 = -INFINITY, l0 = 0.0f, l1 = 0.0f;
    float oacc[8][4];
#pragma unroll
    for (int nt = 0; nt < 8; nt++)
#pragma unroll
        for (int i = 0; i < 4; i++) oacc[nt][i] = 0.0f;

    const int NB = SEQ / 64;  // 32
    for (int kb = 0; kb < NB; kb++) {
        const int p = kb & 1;
        if (kb < NB - 2) cp_wait<1>(); else cp_wait<0>();
        __syncthreads();

        // S = Q @ K^T
        float s[8][4];
#pragma unroll
        for (int nt = 0; nt < 8; nt++)
#pragma unroll
            for (int i = 0; i < 4; i++) s[nt][i] = 0.0f;

        const float* Kp = Ks + p * 64 * KP;
#pragma unroll
        for (int kk = 0; kk < 8; kk++) {
#pragma unroll
            for (int nt = 0; nt < 8; nt++) {
                uint32_t b0 = fbits(Kp[(nt * 8 + g) * KP + kk * 8 + tig]);
                uint32_t b1 = fbits(Kp[(nt * 8 + g) * KP + kk * 8 + tig + 4]);
                mma8(s[nt], qa[kk][0], qa[kk][1], qa[kk][2], qa[kk][3], b0, b1);
            }
        }

        // Online softmax on fragment rows r0=qb+g, r1=qb+g+8
        float rmax0 = -INFINITY, rmax1 = -INFINITY;
#pragma unroll
        for (int nt = 0; nt < 8; nt++) {
            rmax0 = fmaxf(rmax0, fmaxf(s[nt][0], s[nt][1]));
            rmax1 = fmaxf(rmax1, fmaxf(s[nt][2], s[nt][3]));
        }
        rmax0 = fmaxf(rmax0, __shfl_xor_sync(0xffffffffu, rmax0, 1));
        rmax0 = fmaxf(rmax0, __shfl_xor_sync(0xffffffffu, rmax0, 2));
        rmax1 = fmaxf(rmax1, __shfl_xor_sync(0xffffffffu, rmax1, 1));
        rmax1 = fmaxf(rmax1, __shfl_xor_sync(0xffffffffu, rmax1, 2));

        const float mn0 = fmaxf(m0, rmax0);
        const float mn1 = fmaxf(m1, rmax1);
        const float alpha0 = __expf(m0 - mn0);
        const float alpha1 = __expf(m1 - mn1);

        float rs0 = 0.0f, rs1 = 0.0f;
#pragma unroll
        for (int nt = 0; nt < 8; nt++) {
            float p0 = __expf(s[nt][0] - mn0);
            float p1 = __expf(s[nt][1] - mn0);
            float p2 = __expf(s[nt][2] - mn1);
            float p3 = __expf(s[nt][3] - mn1);
            rs0 += p0 + p1;
            rs1 += p2 + p3;
            *(float2*)&Ps[(qb + g) * PP + nt * 8 + 2 * tig] =
                make_float2(f2tf32f(p0), f2tf32f(p1));
            *(float2*)&Ps[(qb + g + 8) * PP + nt * 8 + 2 * tig] =
                make_float2(f2tf32f(p2), f2tf32f(p3));
        }
        rs0 += __shfl_xor_sync(0xffffffffu, rs0, 1);
        rs0 += __shfl_xor_sync(0xffffffffu, rs0, 2);
        rs1 += __shfl_xor_sync(0xffffffffu, rs1, 1);
        rs1 += __shfl_xor_sync(0xffffffffu, rs1, 2);

        l0 = l0 * alpha0 + rs0;
        l1 = l1 * alpha1 + rs1;
        m0 = mn0; m1 = mn1;
#pragma unroll
        for (int nt = 0; nt < 8; nt++) {
            oacc[nt][0] *= alpha0; oacc[nt][1] *= alpha0;
            oacc[nt][2] *= alpha1; oacc[nt][3] *= alpha1;
        }

        // PV: oacc += P @ V  (P rows are this warp's own rows)
        __syncwarp();
        const float* Vp = Vs + p * 64 * VP;
#pragma unroll
        for (int kk = 0; kk < 8; kk++) {
            uint32_t pa0 = fbits(Ps[(qb + g) * PP + kk * 8 + tig]);
            uint32_t pa1 = fbits(Ps[(qb + g + 8) * PP + kk * 8 + tig]);
            uint32_t pa2 = fbits(Ps[(qb + g) * PP + kk * 8 + tig + 4]);
            uint32_t pa3 = fbits(Ps[(qb + g + 8) * PP + kk * 8 + tig + 4]);
#pragma unroll
            for (int nt = 0; nt < 8; nt++) {
                uint32_t b0 = fbits(Vp[(kk * 8 + tig) * VP + nt * 8 + g]);
                uint32_t b1 = fbits(Vp[(kk * 8 + tig + 4) * VP + nt * 8 + g]);
                mma8(oacc[nt], pa0, pa1, pa2, pa3, b0, b1);
            }
        }
        __syncthreads();   // everyone done with buf p before refilling it
        if (kb + 2 < NB) load_blk(kb + 2, p);
    }

    // Epilogue: O rows (tf32-rounded for the O-projection's raw-bit path)
    const float inv0 = 1.0f / l0;
    const float inv1 = 1.0f / l1;
#pragma unroll
    for (int nt = 0; nt < 8; nt++) {
        const int col = nt * 8 + 2 * tig;
        const size_t ro0 = base + (size_t)(q0 + qb + g) * D_MODEL + col;
        const size_t ro1 = base + (size_t)(q0 + qb + g + 8) * D_MODEL + col;
        *(float2*)(O + ro0) = make_float2(f2tf32f(oacc[nt][0] * inv0),
                                          f2tf32f(oacc[nt][1] * inv0));
        *(float2*)(O + ro1) = make_float2(f2tf32f(oacc[nt][2] * inv1),
                                          f2tf32f(oacc[nt][3] * inv1));
    }
}

// ---------------------------------------------------------------------------
// Launch
// ---------------------------------------------------------------------------
extern "C" void kernel_launch(void* const* d_in, const int* in_sizes, int n_in,
                              void* d_out, int out_size)
{
    const float* q  = (const float*)d_in[0];
    const float* k  = (const float*)d_in[1];
    const float* v  = (const float*)d_in[2];
    const float* Wq = (const float*)d_in[3];
    const float* bq = (const float*)d_in[4];
    const float* Wk = (const float*)d_in[5];
    const float* bk = (const float*)d_in[6];
    const float* Wv = (const float*)d_in[7];
    const float* bv = (const float*)d_in[8];
    const float* Wo = (const float*)d_in[9];
    const float* bo = (const float*)d_in[10];
    float* out = (float*)d_out;

    float *pQ, *pK, *pV, *pO;
    cudaGetSymbolAddress((void**)&pQ, g_Q);
    cudaGetSymbolAddress((void**)&pK, g_K);
    cudaGetSymbolAddress((void**)&pV, g_V);
    cudaGetSymbolAddress((void**)&pO, g_O);

    cudaFuncSetAttribute(attn_mma, cudaFuncAttributeMaxDynamicSharedMemorySize,
                         ATTN_SMEM);

    dim3 gGemm(D_MODEL / 128, MTOT / 128);  // (8, 64)
    gemm_mma<<<gGemm, 256>>>(q, Wq, bq, pQ, 1);
    gemm_mma<<<gGemm, 256>>>(k, Wk, bk, pK, 1);
    gemm_mma<<<gGemm, 256>>>(v, Wv, bv, pV, 1);

    dim3 gAttn(SEQ / 128, BATCH * NUM_HEADS);  // (16, 64)
    attn_mma<<<gAttn, 256, ATTN_SMEM>>>(pQ, pK, pV, pO);

    gemm_mma<<<gGemm, 256>>>(pO, Wo, bo, out, 0);
}

// round 4
// speedup vs baseline: 4.6066x; 1.0786x over previous
#include <cuda_runtime.h>
#include <math.h>
#include <stdint.h>

#define D_MODEL 1024
#define NUM_HEADS 16
#define DK 64
#define BATCH 4
#define SEQ 2048
#define MTOT (BATCH * SEQ)   // 8192

// Scratch (no allocation allowed)
__device__ float g_Q[MTOT * D_MODEL];
__device__ float g_K[MTOT * D_MODEL];
__device__ float g_V[MTOT * D_MODEL];
__device__ float g_O[MTOT * D_MODEL];

// ---------------------------------------------------------------------------
// Helpers
// ---------------------------------------------------------------------------
__device__ __forceinline__ uint32_t f2tf32(float x) {
    uint32_t r;
    asm("cvt.rn.tf32.f32 %0, %1;" : "=r"(r) : "f"(x));
    return r;
}
__device__ __forceinline__ float f2tf32f(float x) {
    return __uint_as_float(f2tf32(x));
}
__device__ __forceinline__ uint32_t u2tf32(uint32_t u) {
    return f2tf32(__uint_as_float(u));
}
__device__ __forceinline__ uint32_t fbits(float x) { return __float_as_uint(x); }

// D += A*B : m16n8k8 tf32.
// a regs: (g,tig),(g+8,tig),(g,tig+4),(g+8,tig+4); b regs: (k=tig,n=g),(k=tig+4,n=g)
// c regs: (g,2tig),(g,2tig+1),(g+8,2tig),(g+8,2tig+1)
__device__ __forceinline__ void mma8(float c[4], uint32_t a0, uint32_t a1,
                                     uint32_t a2, uint32_t a3,
                                     uint32_t b0, uint32_t b1) {
    asm volatile(
        "mma.sync.aligned.m16n8k8.row.col.f32.tf32.tf32.f32 "
        "{%0,%1,%2,%3}, {%4,%5,%6,%7}, {%8,%9}, {%0,%1,%2,%3};"
        : "+f"(c[0]), "+f"(c[1]), "+f"(c[2]), "+f"(c[3])
        : "r"(a0), "r"(a1), "r"(a2), "r"(a3), "r"(b0), "r"(b1));
}

__device__ __forceinline__ void ldsm4(uint32_t r[4], uint32_t saddr) {
    asm volatile(
        "ldmatrix.sync.aligned.m8n8.x4.shared.b16 {%0,%1,%2,%3}, [%4];"
        : "=r"(r[0]), "=r"(r[1]), "=r"(r[2]), "=r"(r[3]) : "r"(saddr));
}

__device__ __forceinline__ void cp_async16(void* smem, const void* gmem) {
    uint32_t s = (uint32_t)__cvta_generic_to_shared(smem);
    asm volatile("cp.async.cg.shared.global [%0], [%1], 16;" :: "r"(s), "l"(gmem));
}
__device__ __forceinline__ void cp_commit() {
    asm volatile("cp.async.commit_group;");
}
template <int N>
__device__ __forceinline__ void cp_wait() {
    asm volatile("cp.async.wait_group %0;" :: "n"(N));
}

// ---------------------------------------------------------------------------
// GEMM v2: C[8192,1024] = A @ W^T + bias. tf32 mma, cp.async 4-stage,
// ldmatrix fragments, in-register RN tf32 conversion.
// CTA 128x128, 8 warps (4 row x 2 col), warp tile 32x64, BK=16.
// ---------------------------------------------------------------------------
#define GPITCH 20                         // floats; 80B rows, 16B aligned
#define GSTG   4
#define GSTAGE (128 * GPITCH)             // floats per matrix per stage
#define GEMM_SMEM (GSTG * 2 * GSTAGE * 4) // 81920 B

__global__ __launch_bounds__(256, 2) void gemm_mma(
    const float* __restrict__ A, const float* __restrict__ W,
    const float* __restrict__ bias, float* __restrict__ C, int round_out)
{
    extern __shared__ __align__(16) float sg[];
    float* As = sg;
    float* Ws = sg + GSTG * GSTAGE;

    const int tid = threadIdx.x;
    const int lane = tid & 31;
    const int g = lane >> 2, tig = lane & 3;
    const int wid = tid >> 5;
    const int wm = wid & 3;      // row block (32 rows)
    const int wn = wid >> 2;     // col block (64 cols)
    const int row0 = blockIdx.y * 128;
    const int col0 = blockIdx.x * 128;

    const float* Ag = A + (size_t)row0 * D_MODEL;
    const float* Wg = W + (size_t)col0 * D_MODEL;

    const uint32_t sA = (uint32_t)__cvta_generic_to_shared(As);
    const uint32_t sW = (uint32_t)__cvta_generic_to_shared(Ws);

    // cp.async stage loader: 128 rows x 16 floats per matrix = 512 x 16B
    auto load_stage = [&](int ch, int st) {
        const int kof = ch * 16;
#pragma unroll
        for (int j = 0; j < 2; j++) {
            int slot = tid + j * 256;
            int r = slot >> 2, c = (slot & 3) * 4;
            cp_async16(&As[st * GSTAGE + r * GPITCH + c],
                       Ag + (size_t)r * D_MODEL + kof + c);
            cp_async16(&Ws[st * GSTAGE + r * GPITCH + c],
                       Wg + (size_t)r * D_MODEL + kof + c);
        }
        cp_commit();
    };
    load_stage(0, 0);
    load_stage(1, 1);
    load_stage(2, 2);

    float acc[2][8][4];
#pragma unroll
    for (int mt = 0; mt < 2; mt++)
#pragma unroll
        for (int nt = 0; nt < 8; nt++)
#pragma unroll
            for (int i = 0; i < 4; i++) acc[mt][nt][i] = 0.0f;

    // ldmatrix per-lane addressing (A-style and B-style quadrant layouts)
    const int a_row = lane & 15;
    const int a_byt = (lane >> 4) << 4;
    const int b_row = ((lane >> 4) << 3) + (lane & 7);
    const int b_byt = ((lane >> 3) & 1) << 4;

    for (int ch = 0; ch < 64; ch++) {
        const int p = ch & 3;
        if (ch < 62) cp_wait<2>();
        else if (ch == 62) cp_wait<1>();
        else cp_wait<0>();
        __syncthreads();
        if (ch + 3 < 64) load_stage(ch + 3, (ch + 3) & 3);

        const uint32_t aBase = sA + p * (GSTAGE * 4);
        const uint32_t wBase = sW + p * (GSTAGE * 4);
#pragma unroll
        for (int kk = 0; kk < 2; kk++) {
            uint32_t ua[2][4];
#pragma unroll
            for (int mt = 0; mt < 2; mt++) {
                ldsm4(ua[mt], aBase + (wm * 32 + mt * 16 + a_row) * (GPITCH * 4)
                              + kk * 32 + a_byt);
#pragma unroll
                for (int i = 0; i < 4; i++) ua[mt][i] = u2tf32(ua[mt][i]);
            }
#pragma unroll
            for (int nt2 = 0; nt2 < 4; nt2++) {
                uint32_t ub[4];
                ldsm4(ub, wBase + (wn * 64 + nt2 * 16 + b_row) * (GPITCH * 4)
                          + kk * 32 + b_byt);
#pragma unroll
                for (int i = 0; i < 4; i++) ub[i] = u2tf32(ub[i]);
                mma8(acc[0][nt2 * 2],     ua[0][0], ua[0][1], ua[0][2], ua[0][3], ub[0], ub[1]);
                mma8(acc[1][nt2 * 2],     ua[1][0], ua[1][1], ua[1][2], ua[1][3], ub[0], ub[1]);
                mma8(acc[0][nt2 * 2 + 1], ua[0][0], ua[0][1], ua[0][2], ua[0][3], ub[2], ub[3]);
                mma8(acc[1][nt2 * 2 + 1], ua[1][0], ua[1][1], ua[1][2], ua[1][3], ub[2], ub[3]);
            }
        }
    }

    // Epilogue
#pragma unroll
    for (int mt = 0; mt < 2; mt++) {
        const int ra = row0 + wm * 32 + mt * 16 + g;
#pragma unroll
        for (int nt = 0; nt < 8; nt++) {
            const int col = col0 + wn * 64 + nt * 8 + 2 * tig;
            const float bz0 = bias[col], bz1 = bias[col + 1];
            float v0 = acc[mt][nt][0] + bz0, v1 = acc[mt][nt][1] + bz1;
            float v2 = acc[mt][nt][2] + bz0, v3 = acc[mt][nt][3] + bz1;
            if (round_out) {
                v0 = f2tf32f(v0); v1 = f2tf32f(v1);
                v2 = f2tf32f(v2); v3 = f2tf32f(v3);
            }
            *(float2*)(C + (size_t)ra * D_MODEL + col) = make_float2(v0, v1);
            *(float2*)(C + (size_t)(ra + 8) * D_MODEL + col) = make_float2(v2, v3);
        }
    }
}

// ---------------------------------------------------------------------------
// Flash attention v2: CTA per (b,h,128 q-rows), Bc=64, 8 warps x 16 rows.
// Q/K fragments via ldmatrix (inputs already tf32 from projections).
// P held in registers; PV A-fragments built via intra-quad shuffles.
// smem: K[2][64*68] | V[2][64*72]; Q staged over the K region pre-loop.
// ---------------------------------------------------------------------------
#define KP 68
#define VP 72
#define ATTN_SMEM ((2 * 64 * KP + 2 * 64 * VP) * 4)  // 71680 B

__global__ __launch_bounds__(256, 1) void attn_mma(
    const float* __restrict__ Q, const float* __restrict__ K,
    const float* __restrict__ V, float* __restrict__ O)
{
    extern __shared__ __align__(16) float smf[];
    float* Ks = smf;                    // 2 * 64*KP
    float* Vs = smf + 2 * 64 * KP;      // 2 * 64*VP
    float* Qst = smf;                   // overlay: 128*KP == 2*64*KP

    const int tid = threadIdx.x;
    const int lane = tid & 31;
    const int g = lane >> 2, tig = lane & 3;
    const int wid = tid >> 5;
    const int qb = wid * 16;

    const int b = blockIdx.y >> 4;
    const int h = blockIdx.y & 15;
    const int q0 = blockIdx.x * 128;
    const size_t base = (size_t)b * SEQ * D_MODEL + (size_t)h * DK;

    // Stage Q (scaled by 1/8, pow2 -> still tf32-exact) and lift fragments.
    for (int i = tid; i < 128 * 16; i += 256) {
        int r = i >> 4, c4 = (i & 15) * 4;
        float4 qv = *(const float4*)(Q + base + (size_t)(q0 + r) * D_MODEL + c4);
        qv.x *= 0.125f; qv.y *= 0.125f; qv.z *= 0.125f; qv.w *= 0.125f;
        *(float4*)&Qst[r * KP + c4] = qv;
    }
    __syncthreads();

    const uint32_t sQ = (uint32_t)__cvta_generic_to_shared(Qst);
    const uint32_t sK = (uint32_t)__cvta_generic_to_shared(Ks);
    const int a_row = lane & 15;
    const int a_byt = (lane >> 4) << 4;
    const int b_row = ((lane >> 4) << 3) + (lane & 7);
    const int b_byt = ((lane >> 3) & 1) << 4;

    uint32_t qa[8][4];
#pragma unroll
    for (int kk = 0; kk < 8; kk++)
        ldsm4(qa[kk], sQ + (qb + a_row) * (KP * 4) + kk * 32 + a_byt);
    __syncthreads();

    // cp.async K/V block loader
    auto load_blk = [&](int kb, int p) {
#pragma unroll
        for (int j = 0; j < 4; j++) {
            int slot = tid + j * 256;
            int r = slot >> 4, c4 = (slot & 15) * 4;
            const float* kg = K + base + (size_t)(kb * 64 + r) * D_MODEL + c4;
            const float* vg = V + base + (size_t)(kb * 64 + r) * D_MODEL + c4;
            cp_async16(&Ks[p * 64 * KP + r * KP + c4], kg);
            cp_async16(&Vs[p * 64 * VP + r * VP + c4], vg);
        }
        cp_commit();
    };
    load_blk(0, 0);
    load_blk(1, 1);

    float m0 = -INFINITY, m1 = -INFINITY, l0 = 0.0f, l1 = 0.0f;
    float oacc[8][4];
#pragma unroll
    for (int nt = 0; nt < 8; nt++)
#pragma unroll
        for (int i = 0; i < 4; i++) oacc[nt][i] = 0.0f;

    const int NB = SEQ / 64;  // 32
    for (int kb = 0; kb < NB; kb++) {
        const int p = kb & 1;
        if (kb < NB - 2) cp_wait<1>(); else cp_wait<0>();
        __syncthreads();

        // S = Q @ K^T (fragments raw: both operands already tf32-valued)
        float s[8][4];
#pragma unroll
        for (int nt = 0; nt < 8; nt++)
#pragma unroll
            for (int i = 0; i < 4; i++) s[nt][i] = 0.0f;

        const uint32_t kBase = sK + p * (64 * KP * 4);
#pragma unroll
        for (int kk = 0; kk < 8; kk++) {
#pragma unroll
            for (int nt2 = 0; nt2 < 4; nt2++) {
                uint32_t ub[4];
                ldsm4(ub, kBase + (nt2 * 16 + b_row) * (KP * 4) + kk * 32 + b_byt);
                mma8(s[nt2 * 2],     qa[kk][0], qa[kk][1], qa[kk][2], qa[kk][3], ub[0], ub[1]);
                mma8(s[nt2 * 2 + 1], qa[kk][0], qa[kk][1], qa[kk][2], qa[kk][3], ub[2], ub[3]);
            }
        }

        // Online softmax on fragment rows r0=qb+g, r1=qb+g+8
        float rmax0 = -INFINITY, rmax1 = -INFINITY;
#pragma unroll
        for (int nt = 0; nt < 8; nt++) {
            rmax0 = fmaxf(rmax0, fmaxf(s[nt][0], s[nt][1]));
            rmax1 = fmaxf(rmax1, fmaxf(s[nt][2], s[nt][3]));
        }
        rmax0 = fmaxf(rmax0, __shfl_xor_sync(0xffffffffu, rmax0, 1));
        rmax0 = fmaxf(rmax0, __shfl_xor_sync(0xffffffffu, rmax0, 2));
        rmax1 = fmaxf(rmax1, __shfl_xor_sync(0xffffffffu, rmax1, 1));
        rmax1 = fmaxf(rmax1, __shfl_xor_sync(0xffffffffu, rmax1, 2));

        const float mn0 = fmaxf(m0, rmax0);
        const float mn1 = fmaxf(m1, rmax1);
        const float alpha0 = __expf(m0 - mn0);
        const float alpha1 = __expf(m1 - mn1);

        float rs0 = 0.0f, rs1 = 0.0f;
#pragma unroll
        for (int nt = 0; nt < 8; nt++) {
            s[nt][0] = __expf(s[nt][0] - mn0);
            s[nt][1] = __expf(s[nt][1] - mn0);
            s[nt][2] = __expf(s[nt][2] - mn1);
            s[nt][3] = __expf(s[nt][3] - mn1);
            rs0 += s[nt][0] + s[nt][1];
            rs1 += s[nt][2] + s[nt][3];
        }
        rs0 += __shfl_xor_sync(0xffffffffu, rs0, 1);
        rs0 += __shfl_xor_sync(0xffffffffu, rs0, 2);
        rs1 += __shfl_xor_sync(0xffffffffu, rs1, 1);
        rs1 += __shfl_xor_sync(0xffffffffu, rs1, 2);

        l0 = l0 * alpha0 + rs0;
        l1 = l1 * alpha1 + rs1;
        m0 = mn0; m1 = mn1;
#pragma unroll
        for (int nt = 0; nt < 8; nt++) {
            oacc[nt][0] *= alpha0; oacc[nt][1] *= alpha0;
            oacc[nt][2] *= alpha1; oacc[nt][3] *= alpha1;
        }

        // PV: A-fragments built from S C-frags by intra-quad shuffle.
        const float* Vp = Vs + p * 64 * VP;
        const int src0 = (lane & ~3) | (tig >> 1);
        const int src1 = src0 + 2;
        const bool odd = (tig & 1);
#pragma unroll
        for (int kk = 0; kk < 8; kk++) {
            float t00 = __shfl_sync(0xffffffffu, s[kk][0], src0);
            float t01 = __shfl_sync(0xffffffffu, s[kk][1], src0);
            float t02 = __shfl_sync(0xffffffffu, s[kk][2], src0);
            float t03 = __shfl_sync(0xffffffffu, s[kk][3], src0);
            float t10 = __shfl_sync(0xffffffffu, s[kk][0], src1);
            float t11 = __shfl_sync(0xffffffffu, s[kk][1], src1);
            float t12 = __shfl_sync(0xffffffffu, s[kk][2], src1);
            float t13 = __shfl_sync(0xffffffffu, s[kk][3], src1);
            uint32_t a0 = f2tf32(odd ? t01 : t00);
            uint32_t a1 = f2tf32(odd ? t03 : t02);
            uint32_t a2 = f2tf32(odd ? t11 : t10);
            uint32_t a3 = f2tf32(odd ? t13 : t12);
#pragma unroll
            for (int nt = 0; nt < 8; nt++) {
                uint32_t b0 = fbits(Vp[(kk * 8 + tig) * VP + nt * 8 + g]);
                uint32_t b1 = fbits(Vp[(kk * 8 + tig + 4) * VP + nt * 8 + g]);
                mma8(oacc[nt], a0, a1, a2, a3, b0, b1);
            }
        }
        __syncthreads();   // all warps done with buffer p before refill
        if (kb + 2 < NB) load_blk(kb + 2, p);
    }

    // Epilogue (plain fp32; O-projection GEMM does the tf32 RN conversion)
    const float inv0 = 1.0f / l0;
    const float inv1 = 1.0f / l1;
#pragma unroll
    for (int nt = 0; nt < 8; nt++) {
        const int col = nt * 8 + 2 * tig;
        const size_t ro0 = base + (size_t)(q0 + qb + g) * D_MODEL + col;
        const size_t ro1 = base + (size_t)(q0 + qb + g + 8) * D_MODEL + col;
        *(float2*)(O + ro0) = make_float2(oacc[nt][0] * inv0, oacc[nt][1] * inv0);
        *(float2*)(O + ro1) = make_float2(oacc[nt][2] * inv1, oacc[nt][3] * inv1);
    }
}

// ---------------------------------------------------------------------------
// Launch
// ---------------------------------------------------------------------------
extern "C" void kernel_launch(void* const* d_in, const int* in_sizes, int n_in,
                              void* d_out, int out_size)
{
    const float* q  = (const float*)d_in[0];
    const float* k  = (const float*)d_in[1];
    const float* v  = (const float*)d_in[2];
    const float* Wq = (const float*)d_in[3];
    const float* bq = (const float*)d_in[4];
    const float* Wk = (const float*)d_in[5];
    const float* bk = (const float*)d_in[6];
    const float* Wv = (const float*)d_in[7];
    const float* bv = (const float*)d_in[8];
    const float* Wo = (const float*)d_in[9];
    const float* bo = (const float*)d_in[10];
    float* out = (float*)d_out;

    float *pQ, *pK, *pV, *pO;
    cudaGetSymbolAddress((void**)&pQ, g_Q);
    cudaGetSymbolAddress((void**)&pK, g_K);
    cudaGetSymbolAddress((void**)&pV, g_V);
    cudaGetSymbolAddress((void**)&pO, g_O);

    cudaFuncSetAttribute(gemm_mma, cudaFuncAttributeMaxDynamicSharedMemorySize,
                         GEMM_SMEM);
    cudaFuncSetAttribute(attn_mma, cudaFuncAttributeMaxDynamicSharedMemorySize,
                         ATTN_SMEM);

    dim3 gGemm(D_MODEL / 128, MTOT / 128);  // (8, 64)
    gemm_mma<<<gGemm, 256, GEMM_SMEM>>>(q, Wq, bq, pQ, 1);
    gemm_mma<<<gGemm, 256, GEMM_SMEM>>>(k, Wk, bk, pK, 1);
    gemm_mma<<<gGemm, 256, GEMM_SMEM>>>(v, Wv, bv, pV, 1);

    dim3 gAttn(SEQ / 128, BATCH * NUM_HEADS);  // (16, 64)
    attn_mma<<<gAttn, 256, ATTN_SMEM>>>(pQ, pK, pV, pO);

    gemm_mma<<<gGemm, 256, GEMM_SMEM>>>(pO, Wo, bo, out, 0);
}